// round 17
// baseline (speedup 1.0000x reference)
#include <cuda_runtime.h>
#include <stdint.h>

// Problem constants
#define BB 16
#define CC 4
#define HH 512
#define WW 1024
#define ROWS (BB * CC * HH)       // 32768
#define NBLK (ROWS / 16)          // 2048 blocks, 16 rows each (2 per warp)
#define BCN  (BB * CC)            // 64 (b,c) groups; 32 blocks per group

// ---------------------------------------------------------------------------
// Kernel A (primary, 1 block): zero the output scalar, release-fence, then
// trigger the dependent grid (PDL). Proven-overlapped (~0.5us exposed).
// ---------------------------------------------------------------------------
__global__ void zero_out_kernel(float* __restrict__ out)
{
    if (threadIdx.x == 0) {
        out[0] = 0.0f;
        __threadfence();
        asm volatile("griddepcontrol.launch_dependents;");
    }
}

// ---------------------------------------------------------------------------
// Kernel B (dependent, streaming, 2 rows per warp — software pipelined):
//   1. Front-batch 16 float4 loads (rows A and B, 8KB/warp) -> deep MLP.
//   2. Scan A (serial first-max chain) + warp-reduce.
//   3. Lane 0 issues gather A (pred/true/vertical) — latency overlapped by:
//   4. Scan B + warp-reduce.
//   5. Lane 0 consumes gather A, issues + consumes gather B.
//   6. One __syncthreads; warp 0 recounts the group's masked rows (L2-hot
//      2KB) and fires ONE fire-and-forget RED into out. No acquires, no
//      with-return atomics, no trailing node.
// ---------------------------------------------------------------------------
__global__ __launch_bounds__(256) void row_argmax_kernel(
    const float* __restrict__ offset_pred,
    const float* __restrict__ offset_true,
    const float* __restrict__ cls_true,
    const float* __restrict__ vertical_true,
    float* __restrict__ out)
{
    const int warp_in_block = threadIdx.x >> 5;
    const int lane = threadIdx.x & 31;
    const int rowA = blockIdx.x * 16 + warp_in_block * 2;
    const int rowB = rowA + 1;

    const float4* crowA = reinterpret_cast<const float4*>(cls_true + (size_t)rowA * WW);
    const float4* crowB = reinterpret_cast<const float4*>(cls_true + (size_t)rowB * WW);

    // 1. Front-batch BOTH rows' loads (16x LDG.128 per lane-group).
    float4 a[8], b[8];
#pragma unroll
    for (int k = 0; k < 8; k++) a[k] = __ldcs(&crowA[k * 32 + lane]);
#pragma unroll
    for (int k = 0; k < 8; k++) b[k] = __ldcs(&crowB[k * 32 + lane]);

    const float NEG_INF = -__int_as_float(0x7f800000);

    // 2. Scan A (first-max within lane, increasing index order).
    float bestA = NEG_INF; int idxA = 0;
#pragma unroll
    for (int k = 0; k < 8; k++) {
        const int base = (k * 32 + lane) * 4;
        if (a[k].x > bestA) { bestA = a[k].x; idxA = base + 0; }
        if (a[k].y > bestA) { bestA = a[k].y; idxA = base + 1; }
        if (a[k].z > bestA) { bestA = a[k].z; idxA = base + 2; }
        if (a[k].w > bestA) { bestA = a[k].w; idxA = base + 3; }
    }
#pragma unroll
    for (int off = 16; off > 0; off >>= 1) {
        float ov = __shfl_xor_sync(0xffffffffu, bestA, off);
        int   oi = __shfl_xor_sync(0xffffffffu, idxA, off);
        if (ov > bestA || (ov == bestA && oi < idxA)) { bestA = ov; idxA = oi; }
    }

    // 3. Lane 0: ISSUE gather A now (consumed after scan B -> latency hidden).
    float pA = 0.0f, tA = 0.0f, mA = 0.0f;
    if (lane == 0) {
        const size_t gA = (size_t)rowA * WW + idxA;
        pA = __ldg(&offset_pred[gA]);
        tA = __ldg(&offset_true[gA]);
        mA = (__ldg(&vertical_true[rowA]) >= 0.5f) ? 1.0f : 0.0f;
    }

    // 4. Scan B (overlaps gather-A latency).
    float bestB = NEG_INF; int idxB = 0;
#pragma unroll
    for (int k = 0; k < 8; k++) {
        const int base = (k * 32 + lane) * 4;
        if (b[k].x > bestB) { bestB = b[k].x; idxB = base + 0; }
        if (b[k].y > bestB) { bestB = b[k].y; idxB = base + 1; }
        if (b[k].z > bestB) { bestB = b[k].z; idxB = base + 2; }
        if (b[k].w > bestB) { bestB = b[k].w; idxB = base + 3; }
    }
#pragma unroll
    for (int off = 16; off > 0; off >>= 1) {
        float ov = __shfl_xor_sync(0xffffffffu, bestB, off);
        int   oi = __shfl_xor_sync(0xffffffffu, idxB, off);
        if (ov > bestB || (ov == bestB && oi < idxB)) { bestB = ov; idxB = oi; }
    }

    // 5. Lane 0: consume gather A, issue+consume gather B, publish warp sum.
    __shared__ float s_err[8];
    if (lane == 0) {
        float errA = fabsf(pA - tA) * mA;

        const size_t gB = (size_t)rowB * WW + idxB;
        float pB = __ldg(&offset_pred[gB]);
        float tB = __ldg(&offset_true[gB]);
        float mB = (__ldg(&vertical_true[rowB]) >= 0.5f) ? 1.0f : 0.0f;
        float errB = fabsf(pB - tB) * mB;

        s_err[warp_in_block] = errA + errB;
    }
    __syncthreads();

    // 6. Warp 0 tail: recount the group's masked rows (512 floats, L2-hot),
    //    reduce the block's 8 warp sums, fire ONE REDG.ADD into out.
    if (warp_in_block == 0) {
        const int bc = blockIdx.x >> 5;        // 32 blocks per (b,c) group
        const float4* vt =
            reinterpret_cast<const float4*>(vertical_true + bc * HH);

        float cnt = 0.0f;
#pragma unroll
        for (int j = 0; j < 4; j++) {
            float4 w = __ldg(&vt[j * 32 + lane]);
            cnt += (w.x >= 0.5f) ? 1.0f : 0.0f;
            cnt += (w.y >= 0.5f) ? 1.0f : 0.0f;
            cnt += (w.z >= 0.5f) ? 1.0f : 0.0f;
            cnt += (w.w >= 0.5f) ? 1.0f : 0.0f;
        }
#pragma unroll
        for (int off = 16; off > 0; off >>= 1) {
            cnt += __shfl_xor_sync(0xffffffffu, cnt, off);
        }

        float e = (lane < 8) ? s_err[lane] : 0.0f;
#pragma unroll
        for (int off = 4; off > 0; off >>= 1) {
            e += __shfl_xor_sync(0xffffffffu, e, off);
        }

        if (lane == 0) {
            const float scale = (cnt > 0.0f)
                ? (1.0f / (fmaxf(cnt, 1.0f) * (float)BB)) : 0.0f;
            atomicAdd(out, e * scale);         // REDG.ADD (result unused)
        }
    }
}

// ---------------------------------------------------------------------------
extern "C" void kernel_launch(void* const* d_in, const int* in_sizes, int n_in,
                              void* d_out, int out_size)
{
    const float* offset_pred   = (const float*)d_in[0];
    const float* offset_true   = (const float*)d_in[1];
    const float* cls_true      = (const float*)d_in[2];
    const float* vertical_true = (const float*)d_in[3];
    float* out = (float*)d_out;

    // Primary: zero the scalar, release-fence, trigger dependents.
    zero_out_kernel<<<1, 32>>>(out);

    // Dependent streaming kernel (launches while the tiny primary runs).
    cudaLaunchAttribute attrs[1];
    attrs[0].id = cudaLaunchAttributeProgrammaticStreamSerialization;
    attrs[0].val.programmaticStreamSerializationAllowed = 1;

    cudaLaunchConfig_t cfg = {};
    cfg.gridDim = dim3(NBLK, 1, 1);
    cfg.blockDim = dim3(256, 1, 1);
    cfg.dynamicSmemBytes = 0;
    cfg.stream = 0;
    cfg.attrs = attrs;
    cfg.numAttrs = 1;

    cudaLaunchKernelEx(&cfg, row_argmax_kernel,
                       offset_pred, offset_true, cls_true, vertical_true, out);
}